// round 14
// baseline (speedup 1.0000x reference)
#include <cuda_runtime.h>
#include <cstdint>

// Verblizer: per-token argmax(20) -> expert Linear(2,2) -> softmax(2) -> y,
// plus permuted copy y2 (pu rows first, then non-pu rows in order).
// d_out[0..2S) = y, d_out[2S..4S) = y2.
//
// R13 structure (best): lb_scatter (PDL) + independent streaming blocks,
// CHUNK=1024, u16 smem pu window. R14 deltas:
//   - per-warp ballot lower_bound + membership bitmap rank (replaces the
//     per-token 10-step LDS binary search)
//   - scatter processes 16 pu elements/thread

#define THREADS 256
#define TILE    256
#define NTILES  4
#define CHUNK   (TILE * NTILES)      // 1024 tokens per block
#define MAXB    65537

__device__ int g_lb0[MAXB];

// ---- vectorized streaming scatter: each thread owns pu[16i .. 16i+16) ----
__global__ void lb_scatter(const int* __restrict__ pu, int P, int nblocks)
{
    const int i = blockIdx.x * blockDim.x + threadIdx.x;
    const int base = i * 16;
    if (base < P) {
        int v[17];
        if (base + 16 <= P) {
            #pragma unroll
            for (int q = 0; q < 4; q++) {
                const int4 a = __ldg(reinterpret_cast<const int4*>(pu) + 4 * i + q);
                v[4*q+0] = a.x; v[4*q+1] = a.y; v[4*q+2] = a.z; v[4*q+3] = a.w;
            }
            v[16] = (base + 16 < P) ? __ldg(pu + base + 16) : 0x7fffffff;
        } else {
            #pragma unroll
            for (int k = 0; k <= 16; k++)
                v[k] = (base + k < P) ? __ldg(pu + base + k) : 0x7fffffff;
        }

        if (i == 0) {
            for (int j = 0; j <= nblocks && j * CHUNK <= v[0]; j++) g_lb0[j] = 0;
        }

        #pragma unroll
        for (int k = 0; k < 16; k++) {
            const int m = base + k;
            if (m >= P) break;
            const int hiv = v[k + 1];
            int j  = v[k] / CHUNK + 1;
            int jh = (hiv == 0x7fffffff) ? nblocks : hiv / CHUNK;
            if (jh > nblocks) jh = nblocks;
            for (; j <= jh; j++) g_lb0[j] = m + 1;
        }
    }
    cudaTriggerProgrammaticLaunchCompletion();
}

__device__ __forceinline__ void cp_async16(uint32_t smem_dst, const void* gptr) {
    asm volatile("cp.async.cg.shared.global [%0], [%1], 16;\n" :: "r"(smem_dst), "l"(gptr));
}
__device__ __forceinline__ void cp_commit() { asm volatile("cp.async.commit_group;\n"); }
template<int N> __device__ __forceinline__ void cp_wait() {
    asm volatile("cp.async.wait_group %0;\n" :: "n"(N));
}

// warp-cooperative lower_bound on the smem u16 window (n <= 1024 -> 2 rounds)
__device__ __forceinline__ int warp_lb_smem(const uint16_t* __restrict__ spu,
                                            int n, int target, int lane)
{
    int lo = 0, hi = n;
    while (hi - lo > 32) {
        const int step = (hi - lo + 31) >> 5;
        const int p = lo + lane * step;
        const int v = (p < hi) ? (int)spu[p] : 0x7fffffff;
        const unsigned mask = __ballot_sync(0xffffffffu, v < target);
        if (mask == 0) return lo;            // warp-uniform
        const int lstar = 31 - __clz(mask);
        const int nl = lo + lstar * step;
        hi = min(hi, nl + step);
        lo = nl + 1;
    }
    const int p = lo + lane;
    const int v = (p < hi) ? (int)spu[p] : 0x7fffffff;
    const unsigned mask = __ballot_sync(0xffffffffu, v < target);
    return lo + __popc(mask);
}

__global__ __launch_bounds__(THREADS)
void verblizer_kernel(const float*  __restrict__ x,
                      const float*  __restrict__ h,
                      const float*  __restrict__ W,
                      const float*  __restrict__ b,
                      const int*    __restrict__ pu,
                      int S, int P,
                      float* __restrict__ out)
{
    __shared__ float4   sx[2][TILE * 5];   // 2 x 20KB staged x tiles
    __shared__ uint16_t spu[CHUNK];        // 2KB pu window (offsets from bs)
    __shared__ float4   sW[20];
    __shared__ float2   sB[20];

    const int tid  = threadIdx.x;
    const int lane = tid & 31;
    const int bs   = blockIdx.x * CHUNK;

    // ---- prelude: independent of g_lb0, overlaps the scatter kernel ----
    if (tid < 20) {
        sW[tid] = reinterpret_cast<const float4*>(W)[tid];
        sB[tid] = reinterpret_cast<const float2*>(b)[tid];
    }

    const char* __restrict__ xb = reinterpret_cast<const char*>(x);
    const float2* __restrict__ h2 = reinterpret_cast<const float2*>(h);
    float2* __restrict__ outy  = reinterpret_cast<float2*>(out);
    float2* __restrict__ outy2 = reinterpret_cast<float2*>(out + (size_t)2 * S);

    // stage tile 0 (x stream only)
    {
        const int vt  = min(TILE, S - bs);
        const int vt5 = vt * 5;
        uint32_t dst = (uint32_t)__cvta_generic_to_shared(&sx[0][0]);
        #pragma unroll
        for (int r = 0; r < 5; r++) {
            const int c = tid + r * THREADS;
            if (c < vt5) cp_async16(dst + c * 16, xb + (size_t)bs * 80 + (size_t)c * 16);
        }
        cp_commit();
    }

    // ---- wait for lb_scatter's g_lb0 to be complete & visible ----
    cudaGridDependencySynchronize();

    const int lb0 = g_lb0[blockIdx.x];
    const int n   = g_lb0[blockIdx.x + 1] - lb0;   // pu entries in window (<= CHUNK)
    for (int i = tid; i < n; i += THREADS)
        spu[i] = (uint16_t)(__ldg(pu + lb0 + i) - bs);   // offsets in [0, CHUNK)

    #pragma unroll
    for (int t = 0; t < NTILES; t++) {
        if (t + 1 < NTILES) {
            const int tb  = bs + (t + 1) * TILE;
            const int vt  = min(TILE, S - tb);
            const int vt5 = vt * 5;
            uint32_t dst = (uint32_t)__cvta_generic_to_shared(&sx[(t + 1) & 1][0]);
            #pragma unroll
            for (int r = 0; r < 5; r++) {
                const int c = tid + r * THREADS;
                if (c < vt5) cp_async16(dst + c * 16, xb + (size_t)tb * 80 + (size_t)c * 16);
            }
            cp_commit();
            cp_wait<1>();
        } else {
            cp_wait<0>();
        }
        __syncthreads();

        const int s  = bs + t * TILE + tid;
        const int ls = t * TILE + tid;           // local position in [0, CHUNK)
        float2 yo;

        // NOTE: S % 32 == 0 in this problem family, so (s < S) is warp-uniform;
        // warp-collective ops below are executed by whole warps regardless.
        if (s < S) {
            const float4* __restrict__ row = &sx[t & 1][tid * 5];

            // ---- exact argmax over 20 f32 (first-index tie-break) ----
            const float4 q0 = row[0], q1 = row[1], q2 = row[2], q3 = row[3], q4 = row[4];
            const float g0 = fmaxf(fmaxf(q0.x, q0.y), fmaxf(q0.z, q0.w));
            const float g1 = fmaxf(fmaxf(q1.x, q1.y), fmaxf(q1.z, q1.w));
            const float g2 = fmaxf(fmaxf(q2.x, q2.y), fmaxf(q2.z, q2.w));
            const float g3 = fmaxf(fmaxf(q3.x, q3.y), fmaxf(q3.z, q3.w));
            const float g4 = fmaxf(fmaxf(q4.x, q4.y), fmaxf(q4.z, q4.w));
            const float M  = fmaxf(g4, fmaxf(fmaxf(g0, g1), fmaxf(g2, g3)));

            int gi = 4;
            gi = (g3 == M) ? 3 : gi;
            gi = (g2 == M) ? 2 : gi;
            gi = (g1 == M) ? 1 : gi;
            gi = (g0 == M) ? 0 : gi;

            const float4 qw = row[gi];           // LDS reload of winning quad
            int li = 3;
            li = (qw.z == M) ? 2 : li;
            li = (qw.y == M) ? 1 : li;
            li = (qw.x == M) ? 0 : li;
            const int e = gi * 4 + li;

            // ---- expert Linear(2,2) + softmax(2) ----
            const float2 hv = h2[s];
            const float4 w  = sW[e];
            const float2 bb = sB[e];
            const float y0 = fmaf(hv.x, w.x, fmaf(hv.y, w.y, bb.x));
            const float y1 = fmaf(hv.x, w.z, fmaf(hv.y, w.w, bb.y));
            const float ed  = __expf(y1 - y0);
            const float inv = __fdividef(1.0f, 1.0f + ed);
            yo.x = inv;
            yo.y = ed * inv;

            outy[s] = yo;

            // ---- warp-cooperative permutation rank ----
            const int wb  = ls & ~31;            // warp's first local token
            const int lo0 = warp_lb_smem(spu, n, wb, lane);   // #window entries < wb

            // each lane loads one candidate window entry; entries with value in
            // [wb, wb+32) all lie at indices [lo0, lo0+32) (distinct sorted vals)
            const int idx = lo0 + lane;
            const int ev  = (idx < n) ? (int)spu[idx] : 0x7fffffff;
            const unsigned rel = (unsigned)(ev - wb);
            const unsigned bit = (rel < 32u) ? (1u << rel) : 0u;
            const unsigned bitmap = __reduce_or_sync(0xffffffffu, bit);

            const unsigned below = bitmap & ((1u << lane) - 1u);
            const int  lb   = lb0 + lo0 + __popc(below);
            const bool ispu = (bitmap >> lane) & 1u;
            const int  dest = ispu ? lb : (P + s - lb);
            outy2[dest] = yo;
        }
        __syncthreads();
    }
}

extern "C" void kernel_launch(void* const* d_in, const int* in_sizes, int n_in,
                              void* d_out, int out_size)
{
    const float* x  = (const float*)d_in[0];   // [1, S, 20]
    const float* h  = (const float*)d_in[1];   // [S, 2]
    const float* W  = (const float*)d_in[2];   // [20, 2, 2]
    const float* b  = (const float*)d_in[3];   // [20, 2]
    const int*   pu = (const int*)  d_in[4];   // [P]

    const int S = in_sizes[1] / 2;
    const int P = in_sizes[4];
    const int blocks = (S + CHUNK - 1) / CHUNK;

    const int sthreads = (P + 15) / 16;
    lb_scatter<<<(sthreads + 255) / 256, 256>>>(pu, P, blocks);

    cudaLaunchAttribute attrs[1];
    attrs[0].id = cudaLaunchAttributeProgrammaticStreamSerialization;
    attrs[0].val.programmaticStreamSerializationAllowed = 1;

    cudaLaunchConfig_t cfg = {};
    cfg.gridDim  = dim3((unsigned)blocks, 1, 1);
    cfg.blockDim = dim3(THREADS, 1, 1);
    cfg.dynamicSmemBytes = 0;
    cfg.stream = 0;
    cfg.attrs = attrs;
    cfg.numAttrs = 1;

    cudaLaunchKernelEx(&cfg, verblizer_kernel, x, h, W, b, pu, S, P, (float*)d_out);
}